// round 1
// baseline (speedup 1.0000x reference)
#include <cuda_runtime.h>

// Problem dims
#define DD 1024
#define MM 512
#define CC 256
#define BB 8192
#define NS_ITERS 16

// ---------------- scratch (device globals; no allocation allowed) ----------
__device__ float g_state_p[DD * BB];   // 32 MB
__device__ float g_FS[DD * DD];        // F @ state_cov
__device__ float g_cov_p[DD * DD];
__device__ float g_innov[MM * BB];     // 16 MB
__device__ float g_HP[MM * DD];        // H @ cov_p
__device__ float g_S[MM * MM];
__device__ float g_X[MM * MM];
__device__ float g_X2[MM * MM];
__device__ float g_T[MM * MM];
__device__ float g_PHt[DD * MM];
__device__ float g_K[DD * MM];
__device__ float g_norms[2];

// ---------------- generic row-major SGEMM ----------------------------------
// Cout[m,n] = alpha * sum_k A[m,k] * (TB ? B[n,k] : B[k,n]) + beta * Cin[m,n]
// All dims assumed divisible by the tile sizes (true for this problem).
template <int BM, int BN, int BK, int TM, int TN, bool TB>
__global__ __launch_bounds__(256)
void sgemm(int Mdim, int Ndim, int Kdim,
           const float* __restrict__ A,
           const float* __restrict__ B,
           const float* __restrict__ Cin,
           float* __restrict__ Cout,
           float alpha, float beta)
{
    __shared__ float As[BK][BM];
    __shared__ float Bs[BK][BN + 4];

    constexpr int THREADS = (BM / TM) * (BN / TN);
    const int tid  = threadIdx.x;
    const int brow = blockIdx.y;
    const int bcol = blockIdx.x;
    const int trow = tid / (BN / TN);
    const int tcol = tid % (BN / TN);

    const float* Ab = A + (size_t)brow * BM * Kdim;

    float acc[TM][TN];
#pragma unroll
    for (int i = 0; i < TM; i++)
#pragma unroll
        for (int j = 0; j < TN; j++) acc[i][j] = 0.f;

    // A tile load mapping: float4 along K, scatter-transpose into As[k][m]
    const int aRow = tid / (BK / 4);
    const int aCol = (tid % (BK / 4)) * 4;
    constexpr int A_ROWS_PER = THREADS / (BK / 4);
    // B (no trans): float4 along N
    const int bRow = tid / (BN / 4);
    const int bCol = (tid % (BN / 4)) * 4;
    constexpr int B_ROWS_PER = THREADS / (BN / 4);
    // B (trans): B is N x K row-major; float4 along K, scatter into Bs[k][n]
    const int btRow = tid / (BK / 4);
    const int btCol = (tid % (BK / 4)) * 4;
    constexpr int BT_ROWS_PER = THREADS / (BK / 4);

    for (int k0 = 0; k0 < Kdim; k0 += BK) {
#pragma unroll
        for (int r = 0; r < BM; r += A_ROWS_PER) {
            float4 v = *(const float4*)(Ab + (size_t)(r + aRow) * Kdim + k0 + aCol);
            As[aCol + 0][r + aRow] = v.x;
            As[aCol + 1][r + aRow] = v.y;
            As[aCol + 2][r + aRow] = v.z;
            As[aCol + 3][r + aRow] = v.w;
        }
        if (!TB) {
            const float* Bb = B + (size_t)k0 * Ndim + (size_t)bcol * BN;
#pragma unroll
            for (int r = 0; r < BK; r += B_ROWS_PER) {
                *(float4*)(&Bs[r + bRow][bCol]) =
                    *(const float4*)(Bb + (size_t)(r + bRow) * Ndim + bCol);
            }
        } else {
            const float* Bb = B + (size_t)bcol * BN * Kdim;
#pragma unroll
            for (int r = 0; r < BN; r += BT_ROWS_PER) {
                float4 v = *(const float4*)(Bb + (size_t)(r + btRow) * Kdim + k0 + btCol);
                Bs[btCol + 0][r + btRow] = v.x;
                Bs[btCol + 1][r + btRow] = v.y;
                Bs[btCol + 2][r + btRow] = v.z;
                Bs[btCol + 3][r + btRow] = v.w;
            }
        }
        __syncthreads();

#pragma unroll
        for (int kk = 0; kk < BK; kk++) {
            float ra[TM], rb[TN];
#pragma unroll
            for (int i = 0; i < TM; i++) ra[i] = As[kk][trow * TM + i];
#pragma unroll
            for (int j = 0; j < TN; j++) rb[j] = Bs[kk][tcol * TN + j];
#pragma unroll
            for (int i = 0; i < TM; i++)
#pragma unroll
                for (int j = 0; j < TN; j++) acc[i][j] += ra[i] * rb[j];
        }
        __syncthreads();
    }

#pragma unroll
    for (int i = 0; i < TM; i++) {
        const int gm = brow * BM + trow * TM + i;
#pragma unroll
        for (int j = 0; j < TN; j += 4) {
            const int gn = bcol * BN + tcol * TN + j;
            float4 c;
            c.x = alpha * acc[i][j + 0];
            c.y = alpha * acc[i][j + 1];
            c.z = alpha * acc[i][j + 2];
            c.w = alpha * acc[i][j + 3];
            if (beta != 0.f) {
                float4 p = *(const float4*)(Cin + (size_t)gm * Ndim + gn);
                c.x += beta * p.x; c.y += beta * p.y;
                c.z += beta * p.z; c.w += beta * p.w;
            }
            *(float4*)(Cout + (size_t)gm * Ndim + gn) = c;
        }
    }
}

// ---------------- Newton-Schulz support ------------------------------------
__global__ void zero_norms_kernel(float* norms) {
    if (threadIdx.x < 2) norms[threadIdx.x] = 0.f;
}

// Per-block: abs row sum + abs col sum of S (512x512); atomicMax into norms.
__global__ void snorms_kernel(const float* __restrict__ S, float* norms) {
    __shared__ float sr[256], sc[256];
    const int i = blockIdx.x;
    float r = 0.f, c = 0.f;
    for (int j = threadIdx.x; j < MM; j += 256) {
        r += fabsf(S[(size_t)i * MM + j]);
        c += fabsf(S[(size_t)j * MM + i]);
    }
    sr[threadIdx.x] = r; sc[threadIdx.x] = c;
    __syncthreads();
    for (int o = 128; o > 0; o >>= 1) {
        if (threadIdx.x < o) {
            sr[threadIdx.x] += sr[threadIdx.x + o];
            sc[threadIdx.x] += sc[threadIdx.x + o];
        }
        __syncthreads();
    }
    if (threadIdx.x == 0) {
        atomicMax((int*)&norms[0], __float_as_int(sr[0]));  // positive floats
        atomicMax((int*)&norms[1], __float_as_int(sc[0]));
    }
}

// X0 = S^T / (||S||_inf * ||S||_1)  (guaranteed NS convergence for invertible S)
__global__ void init_X_kernel(const float* __restrict__ S,
                              const float* __restrict__ norms,
                              float* __restrict__ X) {
    const float scale = 1.f / (norms[0] * norms[1]);
    const int idx = blockIdx.x * blockDim.x + threadIdx.x;
    const int i = idx / MM, j = idx % MM;
    X[idx] = S[(size_t)j * MM + i] * scale;
}

// ---------------- host-side dispatch ----------------------------------------
static void gemm(int M, int N, int K,
                 const float* A, const float* B, const float* Cin, float* C,
                 float alpha, float beta, bool tb)
{
    if (M % 128 == 0 && N % 128 == 0 && (M / 128) * (N / 128) >= 128) {
        dim3 g(N / 128, M / 128);
        if (tb) sgemm<128,128,16,8,8,true ><<<g,256>>>(M,N,K,A,B,Cin,C,alpha,beta);
        else    sgemm<128,128,16,8,8,false><<<g,256>>>(M,N,K,A,B,Cin,C,alpha,beta);
    } else {
        dim3 g(N / 64, M / 64);
        if (tb) sgemm<64,64,16,4,4,true ><<<g,256>>>(M,N,K,A,B,Cin,C,alpha,beta);
        else    sgemm<64,64,16,4,4,false><<<g,256>>>(M,N,K,A,B,Cin,C,alpha,beta);
    }
}

extern "C" void kernel_launch(void* const* d_in, const int* in_sizes, int n_in,
                              void* d_out, int out_size)
{
    (void)in_sizes; (void)n_in; (void)out_size;
    const float* state     = (const float*)d_in[0];
    const float* state_cov = (const float*)d_in[1];
    const float* meas      = (const float*)d_in[2];
    const float* control   = (const float*)d_in[3];
    const float* F         = (const float*)d_in[4];
    const float* Q         = (const float*)d_in[5];
    const float* Bc        = (const float*)d_in[6];
    const float* H         = (const float*)d_in[7];
    const float* R         = (const float*)d_in[8];
    float* out_state = (float*)d_out;
    float* out_cov   = out_state + (size_t)DD * BB;

    float *sp, *fs, *cp, *innov, *hp, *S, *X, *X2, *T, *pht, *K, *norms;
    cudaGetSymbolAddress((void**)&sp,    g_state_p);
    cudaGetSymbolAddress((void**)&fs,    g_FS);
    cudaGetSymbolAddress((void**)&cp,    g_cov_p);
    cudaGetSymbolAddress((void**)&innov, g_innov);
    cudaGetSymbolAddress((void**)&hp,    g_HP);
    cudaGetSymbolAddress((void**)&S,     g_S);
    cudaGetSymbolAddress((void**)&X,     g_X);
    cudaGetSymbolAddress((void**)&X2,    g_X2);
    cudaGetSymbolAddress((void**)&T,     g_T);
    cudaGetSymbolAddress((void**)&pht,   g_PHt);
    cudaGetSymbolAddress((void**)&K,     g_K);
    cudaGetSymbolAddress((void**)&norms, g_norms);

    // ---- prediction ----
    // state_p = F @ state + Bc @ control
    gemm(DD, BB, DD, F,  state,   nullptr, sp, 1.f, 0.f, false);
    gemm(DD, BB, CC, Bc, control, sp,      sp, 1.f, 1.f, false);
    // cov_p = F @ state_cov @ F^T + Q
    gemm(DD, DD, DD, F,  state_cov, nullptr, fs, 1.f, 0.f, false);
    gemm(DD, DD, DD, fs, F,         Q,       cp, 1.f, 1.f, true);

    // ---- correction ----
    // innovation = meas - H @ state_p
    gemm(MM, BB, DD, H, sp, meas, innov, -1.f, 1.f, false);
    // HP = H @ cov_p ;  S = HP @ H^T + R
    gemm(MM, DD, DD, H,  cp, nullptr, hp, 1.f, 0.f, false);
    gemm(MM, MM, DD, hp, H,  R,       S,  1.f, 1.f, true);

    // ---- Newton-Schulz inverse of S ----
    zero_norms_kernel<<<1, 32>>>(norms);
    snorms_kernel<<<MM, 256>>>(S, norms);
    init_X_kernel<<<(MM * MM) / 256, 256>>>(S, norms, X);
    float* cur = X;
    float* nxt = X2;
    for (int it = 0; it < NS_ITERS; ++it) {
        gemm(MM, MM, MM, S,   cur, nullptr, T,   1.f, 0.f, false);   // T = S@X
        gemm(MM, MM, MM, cur, T,   cur,     nxt, -1.f, 2.f, false);  // X' = 2X - X@T
        float* tmpp = cur; cur = nxt; nxt = tmpp;
    }
    // cur == S^{-1}

    // kalman_gain = cov_p @ H^T @ S^{-1}
    gemm(DD, MM, DD, cp,  H,   nullptr, pht, 1.f, 0.f, true);
    gemm(DD, MM, MM, pht, cur, nullptr, K,   1.f, 0.f, false);

    // state_n = state_p + K @ innovation
    gemm(DD, BB, MM, K, innov, sp, out_state, 1.f, 1.f, false);
    // cov_n = cov_p - K @ (H @ cov_p)  == (I - K H) cov_p
    gemm(DD, DD, MM, K, hp, cp, out_cov, -1.f, 1.f, false);
}

// round 2
// speedup vs baseline: 1.3098x; 1.3098x over previous
#include <cuda_runtime.h>

// Problem dims
#define DD 1024
#define MM 512
#define CC 256
#define BB 8192
#define NS_ITERS 12

// ---------------- scratch (device globals; no allocation allowed) ----------
__device__ float g_state_p[DD * BB];   // 32 MB
__device__ float g_FS[DD * DD];
__device__ float g_cov_p[DD * DD];
__device__ float g_innov[MM * BB];     // 16 MB
__device__ float g_HP[MM * DD];
__device__ float g_S[MM * MM];
__device__ float g_X[MM * MM];
__device__ float g_X2[MM * MM];
__device__ float g_T[MM * MM];
__device__ float g_PHt[DD * MM];
__device__ float g_K[DD * MM];
__device__ float g_norms[2];

// ---------------- double-buffered row-major SGEMM ---------------------------
// Cout[m,n] = alpha * sum_k A[m,k] * (TB ? B[n,k] : B[k,n]) + beta * Cin[m,n]
// All dims assumed divisible by tile sizes (true for this problem).
template <int BM, int BN, int BK, int TM, int TN, bool TB>
__global__ __launch_bounds__((BM / TM) * (BN / TN))
void sgemm(int Mdim, int Ndim, int Kdim,
           const float* __restrict__ A,
           const float* __restrict__ B,
           const float* __restrict__ Cin,
           float* __restrict__ Cout,
           float alpha, float beta)
{
    constexpr int THREADS = (BM / TM) * (BN / TN);
    __shared__ float As[2][BK][BM];
    __shared__ float Bs[2][BK][BN + 4];

    const int tid  = threadIdx.x;
    const int brow = blockIdx.y;
    const int bcol = blockIdx.x;
    const int trow = tid / (BN / TN);
    const int tcol = tid % (BN / TN);

    const float* Ab = A + (size_t)brow * BM * Kdim;

    // A tile: float4 along K, scatter-transpose into As[k][m]
    const int aRow = tid / (BK / 4);
    const int aCol = (tid % (BK / 4)) * 4;
    constexpr int A_PASS  = (BM * (BK / 4)) / THREADS;
    constexpr int A_RSTEP = THREADS / (BK / 4);
    // B (no trans): float4 along N, straight into Bs[k][n]
    const int bRow = tid / (BN / 4);
    const int bCol = (tid % (BN / 4)) * 4;
    constexpr int B_PASS  = (BK * (BN / 4)) / THREADS;
    constexpr int B_RSTEP = THREADS / (BN / 4);
    // B (trans): B is N x K row-major; float4 along K, scatter into Bs[k][n]
    const int tRow = tid / (BK / 4);
    const int tCol = (tid % (BK / 4)) * 4;
    constexpr int T_PASS  = (BN * (BK / 4)) / THREADS;
    constexpr int T_RSTEP = THREADS / (BK / 4);

    constexpr int BV = TB ? T_PASS : B_PASS;
    float4 ra[A_PASS];
    float4 rb[BV];

    float acc[TM][TN];
#pragma unroll
    for (int i = 0; i < TM; i++)
#pragma unroll
        for (int j = 0; j < TN; j++) acc[i][j] = 0.f;

    auto ldg = [&](int k0) {
#pragma unroll
        for (int p = 0; p < A_PASS; p++)
            ra[p] = *(const float4*)(Ab + (size_t)(p * A_RSTEP + aRow) * Kdim + k0 + aCol);
        if constexpr (!TB) {
            const float* Bb = B + (size_t)k0 * Ndim + (size_t)bcol * BN;
#pragma unroll
            for (int p = 0; p < B_PASS; p++)
                rb[p] = *(const float4*)(Bb + (size_t)(p * B_RSTEP + bRow) * Ndim + bCol);
        } else {
            const float* Bb = B + (size_t)bcol * BN * Kdim;
#pragma unroll
            for (int p = 0; p < T_PASS; p++)
                rb[p] = *(const float4*)(Bb + (size_t)(p * T_RSTEP + tRow) * Kdim + k0 + tCol);
        }
    };

    auto sts = [&](int s) {
#pragma unroll
        for (int p = 0; p < A_PASS; p++) {
            const int m = p * A_RSTEP + aRow;
            As[s][aCol + 0][m] = ra[p].x;
            As[s][aCol + 1][m] = ra[p].y;
            As[s][aCol + 2][m] = ra[p].z;
            As[s][aCol + 3][m] = ra[p].w;
        }
        if constexpr (!TB) {
#pragma unroll
            for (int p = 0; p < B_PASS; p++)
                *(float4*)(&Bs[s][p * B_RSTEP + bRow][bCol]) = rb[p];
        } else {
#pragma unroll
            for (int p = 0; p < T_PASS; p++) {
                const int n = p * T_RSTEP + tRow;
                Bs[s][tCol + 0][n] = rb[p].x;
                Bs[s][tCol + 1][n] = rb[p].y;
                Bs[s][tCol + 2][n] = rb[p].z;
                Bs[s][tCol + 3][n] = rb[p].w;
            }
        }
    };

    ldg(0);
    sts(0);
    __syncthreads();

    int s = 0;
    for (int k0 = 0; k0 < Kdim; k0 += BK) {
        const bool hasNext = (k0 + BK < Kdim);
        if (hasNext) ldg(k0 + BK);

#pragma unroll
        for (int kk = 0; kk < BK; kk++) {
            float ar[TM], br[TN];
#pragma unroll
            for (int i = 0; i < TM; i++) ar[i] = As[s][kk][trow * TM + i];
#pragma unroll
            for (int j = 0; j < TN; j++) br[j] = Bs[s][kk][tcol * TN + j];
#pragma unroll
            for (int i = 0; i < TM; i++)
#pragma unroll
                for (int j = 0; j < TN; j++) acc[i][j] += ar[i] * br[j];
        }

        if (hasNext) {
            sts(s ^ 1);
            __syncthreads();
            s ^= 1;
        }
    }

#pragma unroll
    for (int i = 0; i < TM; i++) {
        const int gm = brow * BM + trow * TM + i;
#pragma unroll
        for (int j = 0; j < TN; j += 4) {
            const int gn = bcol * BN + tcol * TN + j;
            float4 c;
            c.x = alpha * acc[i][j + 0];
            c.y = alpha * acc[i][j + 1];
            c.z = alpha * acc[i][j + 2];
            c.w = alpha * acc[i][j + 3];
            if (beta != 0.f) {
                float4 p = *(const float4*)(Cin + (size_t)gm * Ndim + gn);
                c.x += beta * p.x; c.y += beta * p.y;
                c.z += beta * p.z; c.w += beta * p.w;
            }
            *(float4*)(Cout + (size_t)gm * Ndim + gn) = c;
        }
    }
}

// ---------------- Newton-Schulz support ------------------------------------
__global__ void zero_norms_kernel(float* norms) {
    if (threadIdx.x < 2) norms[threadIdx.x] = 0.f;
}

__global__ void snorms_kernel(const float* __restrict__ S, float* norms) {
    __shared__ float sr[256], sc[256];
    const int i = blockIdx.x;
    float r = 0.f, c = 0.f;
    for (int j = threadIdx.x; j < MM; j += 256) {
        r += fabsf(S[(size_t)i * MM + j]);
        c += fabsf(S[(size_t)j * MM + i]);
    }
    sr[threadIdx.x] = r; sc[threadIdx.x] = c;
    __syncthreads();
    for (int o = 128; o > 0; o >>= 1) {
        if (threadIdx.x < o) {
            sr[threadIdx.x] += sr[threadIdx.x + o];
            sc[threadIdx.x] += sc[threadIdx.x + o];
        }
        __syncthreads();
    }
    if (threadIdx.x == 0) {
        atomicMax((int*)&norms[0], __float_as_int(sr[0]));  // positive floats
        atomicMax((int*)&norms[1], __float_as_int(sc[0]));
    }
}

// X0 = S^T / (||S||_inf * ||S||_1)
__global__ void init_X_kernel(const float* __restrict__ S,
                              const float* __restrict__ norms,
                              float* __restrict__ X) {
    const float scale = 1.f / (norms[0] * norms[1]);
    const int idx = blockIdx.x * blockDim.x + threadIdx.x;
    const int i = idx / MM, j = idx % MM;
    X[idx] = S[(size_t)j * MM + i] * scale;
}

// ---------------- host-side dispatch ----------------------------------------
static void gemm(int M, int N, int K,
                 const float* A, const float* B, const float* Cin, float* C,
                 float alpha, float beta, bool tb)
{
    if (M % 128 == 0 && N % 128 == 0 && (M / 128) * (N / 128) >= 128) {
        dim3 g(N / 128, M / 128);
        if (tb) sgemm<128,128,16,8,8,true ><<<g,256>>>(M,N,K,A,B,Cin,C,alpha,beta);
        else    sgemm<128,128,16,8,8,false><<<g,256>>>(M,N,K,A,B,Cin,C,alpha,beta);
    } else {
        dim3 g(N / 64, M / 64);
        if (tb) sgemm<64,64,16,4,4,true ><<<g,256>>>(M,N,K,A,B,Cin,C,alpha,beta);
        else    sgemm<64,64,16,4,4,false><<<g,256>>>(M,N,K,A,B,Cin,C,alpha,beta);
    }
}

extern "C" void kernel_launch(void* const* d_in, const int* in_sizes, int n_in,
                              void* d_out, int out_size)
{
    (void)in_sizes; (void)n_in; (void)out_size;
    const float* state     = (const float*)d_in[0];
    const float* state_cov = (const float*)d_in[1];
    const float* meas      = (const float*)d_in[2];
    const float* control   = (const float*)d_in[3];
    const float* F         = (const float*)d_in[4];
    const float* Q         = (const float*)d_in[5];
    const float* Bc        = (const float*)d_in[6];
    const float* H         = (const float*)d_in[7];
    const float* R         = (const float*)d_in[8];
    float* out_state = (float*)d_out;
    float* out_cov   = out_state + (size_t)DD * BB;

    float *sp, *fs, *cp, *innov, *hp, *S, *X, *X2, *T, *pht, *K, *norms;
    cudaGetSymbolAddress((void**)&sp,    g_state_p);
    cudaGetSymbolAddress((void**)&fs,    g_FS);
    cudaGetSymbolAddress((void**)&cp,    g_cov_p);
    cudaGetSymbolAddress((void**)&innov, g_innov);
    cudaGetSymbolAddress((void**)&hp,    g_HP);
    cudaGetSymbolAddress((void**)&S,     g_S);
    cudaGetSymbolAddress((void**)&X,     g_X);
    cudaGetSymbolAddress((void**)&X2,    g_X2);
    cudaGetSymbolAddress((void**)&T,     g_T);
    cudaGetSymbolAddress((void**)&pht,   g_PHt);
    cudaGetSymbolAddress((void**)&K,     g_K);
    cudaGetSymbolAddress((void**)&norms, g_norms);

    // ---- prediction ----
    gemm(DD, BB, DD, F,  state,   nullptr, sp, 1.f, 0.f, false);   // F@state
    gemm(DD, BB, CC, Bc, control, sp,      sp, 1.f, 1.f, false);   // + Bc@control
    gemm(DD, DD, DD, F,  state_cov, nullptr, fs, 1.f, 0.f, false); // F@Sigma
    gemm(DD, DD, DD, fs, F,         Q,       cp, 1.f, 1.f, true);  // @F^T + Q

    // ---- correction ----
    gemm(MM, BB, DD, H, sp, meas, innov, -1.f, 1.f, false);        // meas - H@sp
    gemm(MM, DD, DD, H,  cp, nullptr, hp, 1.f, 0.f, false);        // HP
    gemm(MM, MM, DD, hp, H,  R,       S,  1.f, 1.f, true);         // S = HP@H^T + R

    // ---- Newton-Schulz inverse of S ----
    zero_norms_kernel<<<1, 32>>>(norms);
    snorms_kernel<<<MM, 256>>>(S, norms);
    init_X_kernel<<<(MM * MM) / 256, 256>>>(S, norms, X);
    float* cur = X;
    float* nxt = X2;
    for (int it = 0; it < NS_ITERS; ++it) {
        gemm(MM, MM, MM, S,   cur, nullptr, T,   1.f, 0.f, false);   // T = S@X
        gemm(MM, MM, MM, cur, T,   cur,     nxt, -1.f, 2.f, false);  // X' = 2X - X@T
        float* tmpp = cur; cur = nxt; nxt = tmpp;
    }
    // cur == S^{-1}

    // kalman_gain = cov_p @ H^T @ S^{-1}
    gemm(DD, MM, DD, cp,  H,   nullptr, pht, 1.f, 0.f, true);
    gemm(DD, MM, MM, pht, cur, nullptr, K,   1.f, 0.f, false);

    // state_n = state_p + K @ innovation
    gemm(DD, BB, MM, K, innov, sp, out_state, 1.f, 1.f, false);
    // cov_n = cov_p - K @ (H @ cov_p)
    gemm(DD, DD, MM, K, hp, cp, out_cov, -1.f, 1.f, false);
}

// round 6
// speedup vs baseline: 1.5747x; 1.2022x over previous
#include <cuda_runtime.h>
#include <cuda_bf16.h>
#include <cstdint>

// Problem dims
#define DD 1024
#define MM 512
#define CC 256
#define BB 8192
#define NS_ITERS 12

// ---------------- scratch (device globals; no allocation allowed) ----------
__device__ __align__(16) float g_state_p[DD * BB];   // 32 MB
__device__ __align__(16) float g_FS[DD * DD];
__device__ __align__(16) float g_cov_p[DD * DD];
__device__ __align__(16) float g_innov[MM * BB];     // 16 MB
__device__ __align__(16) float g_HP[MM * DD];
__device__ __align__(16) float g_S[MM * MM];
__device__ __align__(16) float g_X[MM * MM];
__device__ __align__(16) float g_X2[MM * MM];
__device__ __align__(16) float g_T[MM * MM];
__device__ __align__(16) float g_PHt[DD * MM];
__device__ __align__(16) float g_K[DD * MM];
__device__ __align__(16) __nv_bfloat16 g_Ah[DD * DD];
__device__ __align__(16) __nv_bfloat16 g_Al[DD * DD];
__device__ __align__(16) __nv_bfloat16 g_Bh[DD * BB];
__device__ __align__(16) __nv_bfloat16 g_Bl[DD * BB];
__device__ __align__(16) float g_norms[2];

// ======================= bf16 split conversion ==============================
__global__ void split_kernel(const float4* __restrict__ in,
                             __nv_bfloat16* __restrict__ hi,
                             __nv_bfloat16* __restrict__ lo, int n4)
{
    int i = blockIdx.x * blockDim.x + threadIdx.x;
    if (i >= n4) return;
    float4 v = in[i];
    __nv_bfloat16 h0 = __float2bfloat16_rn(v.x);
    __nv_bfloat16 h1 = __float2bfloat16_rn(v.y);
    __nv_bfloat16 h2 = __float2bfloat16_rn(v.z);
    __nv_bfloat16 h3 = __float2bfloat16_rn(v.w);
    __nv_bfloat16 l0 = __float2bfloat16_rn(v.x - __bfloat162float(h0));
    __nv_bfloat16 l1 = __float2bfloat16_rn(v.y - __bfloat162float(h1));
    __nv_bfloat16 l2 = __float2bfloat16_rn(v.z - __bfloat162float(h2));
    __nv_bfloat16 l3 = __float2bfloat16_rn(v.w - __bfloat162float(h3));
    ((__nv_bfloat162*)hi)[2 * i + 0] = __nv_bfloat162(h0, h1);
    ((__nv_bfloat162*)hi)[2 * i + 1] = __nv_bfloat162(h2, h3);
    ((__nv_bfloat162*)lo)[2 * i + 0] = __nv_bfloat162(l0, l1);
    ((__nv_bfloat162*)lo)[2 * i + 1] = __nv_bfloat162(l2, l3);
}

// transpose + split: out[c][r] = in[r][c]   (in: R x C, out planes: C x R)
__global__ void splitT_kernel(const float* __restrict__ in,
                              __nv_bfloat16* __restrict__ hi,
                              __nv_bfloat16* __restrict__ lo, int R, int C)
{
    __shared__ float t[32][33];
    const int r0 = blockIdx.y * 32, c0 = blockIdx.x * 32;
    const int tx = threadIdx.x, ty = threadIdx.y;  // 32 x 8
#pragma unroll
    for (int i = 0; i < 32; i += 8)
        t[ty + i][tx] = in[(size_t)(r0 + ty + i) * C + c0 + tx];
    __syncthreads();
#pragma unroll
    for (int i = 0; i < 32; i += 8) {
        float v = t[tx][ty + i];
        __nv_bfloat16 h = __float2bfloat16_rn(v);
        __nv_bfloat16 l = __float2bfloat16_rn(v - __bfloat162float(h));
        size_t o = (size_t)(c0 + ty + i) * R + r0 + tx;
        hi[o] = h;
        lo[o] = l;
    }
}

// ======================= bf16 split-2 tensor-core GEMM ======================
// C = alpha * (Ah+Al) @ (Bh+Bl) (lo*lo dropped) + beta * Cin
// A planes [M,K] row-major; B planes [K,N] row-major. Block 128x128, BK=16.
// 8 warps: warpM=wid/2 (32 rows), warpN=wid%2 (64 cols). NO ldmatrix: all
// fragments via plain 32/16-bit shared loads per the documented m16n8k16
// layout (lane l: g=l>>2, t=l&3).
__device__ __forceinline__ void mma16816(float c[4], const uint32_t a[4],
                                         uint32_t b0, uint32_t b1) {
    asm volatile("mma.sync.aligned.m16n8k16.row.col.f32.bf16.bf16.f32 "
                 "{%0,%1,%2,%3}, {%4,%5,%6,%7}, {%8,%9}, {%0,%1,%2,%3};"
                 : "+f"(c[0]), "+f"(c[1]), "+f"(c[2]), "+f"(c[3])
                 : "r"(a[0]), "r"(a[1]), "r"(a[2]), "r"(a[3]), "r"(b0), "r"(b1));
}

__global__ __launch_bounds__(256)
void bf16gemm(int M, int N, int K,
              const __nv_bfloat16* __restrict__ Ah, const __nv_bfloat16* __restrict__ Al,
              const __nv_bfloat16* __restrict__ Bh, const __nv_bfloat16* __restrict__ Bl,
              const float* __restrict__ Cin, float* __restrict__ Cout,
              float alpha, float beta)
{
    constexpr int SA = 24;    // A smem row stride (elems): 48 B rows, conflict-free frags
    constexpr int SBN = 136;  // B smem row stride (elems): 272 B rows, conflict-free frags
    __shared__ alignas(16) __nv_bfloat16 sAh[128 * SA];
    __shared__ alignas(16) __nv_bfloat16 sAl[128 * SA];
    __shared__ alignas(16) __nv_bfloat16 sBh[16 * SBN];
    __shared__ alignas(16) __nv_bfloat16 sBl[16 * SBN];

    const int tid = threadIdx.x;
    const int wid = tid / 32, lane = tid % 32;
    const int warpM = wid / 2, warpN = wid % 2;
    const int g = lane >> 2, t = lane & 3;
    const int bm = blockIdx.y * 128, bn = blockIdx.x * 128;

    // global->smem mapping, 16B per thread per array
    const int arow = tid >> 1, acol = (tid & 1) * 8;    // 128 rows x 16
    const int brow = tid >> 4, bcol = (tid & 15) * 8;   // 16 rows x 128

    uint4 ra_h, ra_l, rb_h, rb_l;
    auto ldg = [&](int k0) {
        ra_h = *(const uint4*)(Ah + (size_t)(bm + arow) * K + k0 + acol);
        ra_l = *(const uint4*)(Al + (size_t)(bm + arow) * K + k0 + acol);
        rb_h = *(const uint4*)(Bh + (size_t)(k0 + brow) * N + bn + bcol);
        rb_l = *(const uint4*)(Bl + (size_t)(k0 + brow) * N + bn + bcol);
    };
    auto sts = [&]() {
        *(uint4*)(&sAh[arow * SA + acol]) = ra_h;
        *(uint4*)(&sAl[arow * SA + acol]) = ra_l;
        *(uint4*)(&sBh[brow * SBN + bcol]) = rb_h;
        *(uint4*)(&sBl[brow * SBN + bcol]) = rb_l;
    };

    float acc[2][8][4];
#pragma unroll
    for (int mt = 0; mt < 2; mt++)
#pragma unroll
        for (int nt = 0; nt < 8; nt++)
#pragma unroll
            for (int q = 0; q < 4; q++) acc[mt][nt][q] = 0.f;

    const unsigned short* uBh = (const unsigned short*)sBh;
    const unsigned short* uBl = (const unsigned short*)sBl;

    ldg(0);
    for (int k0 = 0; k0 < K; k0 += 16) {
        sts();
        __syncthreads();
        if (k0 + 16 < K) ldg(k0 + 16);

        // A fragments: a0={A[g][2t],A[g][2t+1]}, a1=rows+8, a2/a3 = k+8
        uint32_t ah[2][4], al[2][4];
#pragma unroll
        for (int mt = 0; mt < 2; mt++) {
            const int r = warpM * 32 + mt * 16;
            ah[mt][0] = *(const uint32_t*)&sAh[(r + g) * SA + 2 * t];
            ah[mt][1] = *(const uint32_t*)&sAh[(r + g + 8) * SA + 2 * t];
            ah[mt][2] = *(const uint32_t*)&sAh[(r + g) * SA + 2 * t + 8];
            ah[mt][3] = *(const uint32_t*)&sAh[(r + g + 8) * SA + 2 * t + 8];
            al[mt][0] = *(const uint32_t*)&sAl[(r + g) * SA + 2 * t];
            al[mt][1] = *(const uint32_t*)&sAl[(r + g + 8) * SA + 2 * t];
            al[mt][2] = *(const uint32_t*)&sAl[(r + g) * SA + 2 * t + 8];
            al[mt][3] = *(const uint32_t*)&sAl[(r + g + 8) * SA + 2 * t + 8];
        }
#pragma unroll
        for (int ng = 0; ng < 8; ng++) {
            // B fragments: b0={B[2t][n],B[2t+1][n]}, b1={B[2t+8][n],B[2t+9][n]}
            const int n = warpN * 64 + ng * 8 + g;
            uint32_t bh0 = (uint32_t)uBh[(2 * t) * SBN + n]
                         | ((uint32_t)uBh[(2 * t + 1) * SBN + n] << 16);
            uint32_t bh1 = (uint32_t)uBh[(2 * t + 8) * SBN + n]
                         | ((uint32_t)uBh[(2 * t + 9) * SBN + n] << 16);
            uint32_t bl0 = (uint32_t)uBl[(2 * t) * SBN + n]
                         | ((uint32_t)uBl[(2 * t + 1) * SBN + n] << 16);
            uint32_t bl1 = (uint32_t)uBl[(2 * t + 8) * SBN + n]
                         | ((uint32_t)uBl[(2 * t + 9) * SBN + n] << 16);
#pragma unroll
            for (int mt = 0; mt < 2; mt++) {
                mma16816(acc[mt][ng], ah[mt], bh0, bh1);
                mma16816(acc[mt][ng], ah[mt], bl0, bl1);
                mma16816(acc[mt][ng], al[mt], bh0, bh1);
            }
        }
        __syncthreads();
    }

    // epilogue: c0,c1 at (row g, col 2t,2t+1); c2,c3 at (row g+8, same cols)
#pragma unroll
    for (int mt = 0; mt < 2; mt++) {
        const int rowb = bm + warpM * 32 + mt * 16;
#pragma unroll
        for (int nt = 0; nt < 8; nt++) {
            const int col = bn + warpN * 64 + nt * 8 + 2 * t;
            const int r0 = rowb + g, r1 = rowb + g + 8;
            float2 c01 = make_float2(alpha * acc[mt][nt][0], alpha * acc[mt][nt][1]);
            float2 c23 = make_float2(alpha * acc[mt][nt][2], alpha * acc[mt][nt][3]);
            if (beta != 0.f) {
                float2 p0 = *(const float2*)(Cin + (size_t)r0 * N + col);
                float2 p1 = *(const float2*)(Cin + (size_t)r1 * N + col);
                c01.x += beta * p0.x; c01.y += beta * p0.y;
                c23.x += beta * p1.x; c23.y += beta * p1.y;
            }
            *(float2*)(Cout + (size_t)r0 * N + col) = c01;
            *(float2*)(Cout + (size_t)r1 * N + col) = c23;
        }
    }
}

// ======================= fp32 SIMT SGEMM (Newton-Schulz only) ===============
template <int BM, int BN, int BK, int TM, int TN>
__global__ __launch_bounds__((BM / TM) * (BN / TN))
void sgemm(int Mdim, int Ndim, int Kdim,
           const float* __restrict__ A, const float* __restrict__ B,
           const float* __restrict__ Cin, float* __restrict__ Cout,
           float alpha, float beta)
{
    constexpr int THREADS = (BM / TM) * (BN / TN);
    __shared__ alignas(16) float As[2][BK][BM];
    __shared__ alignas(16) float Bs[2][BK][BN + 4];

    const int tid = threadIdx.x;
    const int brow = blockIdx.y, bcol = blockIdx.x;
    const int trow = tid / (BN / TN), tcol = tid % (BN / TN);
    const float* Ab = A + (size_t)brow * BM * Kdim;

    const int aRow = tid / (BK / 4), aCol = (tid % (BK / 4)) * 4;
    constexpr int A_PASS = (BM * (BK / 4)) / THREADS;
    constexpr int A_RSTEP = THREADS / (BK / 4);
    const int bRow = tid / (BN / 4), bCol = (tid % (BN / 4)) * 4;
    constexpr int B_PASS = (BK * (BN / 4)) / THREADS;
    constexpr int B_RSTEP = THREADS / (BN / 4);

    float4 ra[A_PASS], rb[B_PASS];
    float acc[TM][TN];
#pragma unroll
    for (int i = 0; i < TM; i++)
#pragma unroll
        for (int j = 0; j < TN; j++) acc[i][j] = 0.f;

    auto ldg = [&](int k0) {
#pragma unroll
        for (int p = 0; p < A_PASS; p++)
            ra[p] = *(const float4*)(Ab + (size_t)(p * A_RSTEP + aRow) * Kdim + k0 + aCol);
        const float* Bb = B + (size_t)k0 * Ndim + (size_t)bcol * BN;
#pragma unroll
        for (int p = 0; p < B_PASS; p++)
            rb[p] = *(const float4*)(Bb + (size_t)(p * B_RSTEP + bRow) * Ndim + bCol);
    };
    auto sts = [&](int s) {
#pragma unroll
        for (int p = 0; p < A_PASS; p++) {
            const int m = p * A_RSTEP + aRow;
            As[s][aCol + 0][m] = ra[p].x;
            As[s][aCol + 1][m] = ra[p].y;
            As[s][aCol + 2][m] = ra[p].z;
            As[s][aCol + 3][m] = ra[p].w;
        }
#pragma unroll
        for (int p = 0; p < B_PASS; p++)
            *(float4*)(&Bs[s][p * B_RSTEP + bRow][bCol]) = rb[p];
    };

    ldg(0); sts(0); __syncthreads();
    int s = 0;
    for (int k0 = 0; k0 < Kdim; k0 += BK) {
        const bool hasNext = (k0 + BK < Kdim);
        if (hasNext) ldg(k0 + BK);
#pragma unroll
        for (int kk = 0; kk < BK; kk++) {
            float ar[TM], br[TN];
#pragma unroll
            for (int i = 0; i < TM; i++) ar[i] = As[s][kk][trow * TM + i];
#pragma unroll
            for (int j = 0; j < TN; j++) br[j] = Bs[s][kk][tcol * TN + j];
#pragma unroll
            for (int i = 0; i < TM; i++)
#pragma unroll
                for (int j = 0; j < TN; j++) acc[i][j] += ar[i] * br[j];
        }
        if (hasNext) { sts(s ^ 1); __syncthreads(); s ^= 1; }
    }

#pragma unroll
    for (int i = 0; i < TM; i++) {
        const int gm = brow * BM + trow * TM + i;
#pragma unroll
        for (int j = 0; j < TN; j += 4) {
            const int gn = bcol * BN + tcol * TN + j;
            float4 c;
            c.x = alpha * acc[i][j + 0];
            c.y = alpha * acc[i][j + 1];
            c.z = alpha * acc[i][j + 2];
            c.w = alpha * acc[i][j + 3];
            if (beta != 0.f) {
                float4 p = *(const float4*)(Cin + (size_t)gm * Ndim + gn);
                c.x += beta * p.x; c.y += beta * p.y;
                c.z += beta * p.z; c.w += beta * p.w;
            }
            *(float4*)(Cout + (size_t)gm * Ndim + gn) = c;
        }
    }
}

// ---------------- Newton-Schulz support ------------------------------------
__global__ void zero_norms_kernel(float* norms) {
    if (threadIdx.x < 2) norms[threadIdx.x] = 0.f;
}
__global__ void snorms_kernel(const float* __restrict__ S, float* norms) {
    __shared__ float sr[256], sc[256];
    const int i = blockIdx.x;
    float r = 0.f, c = 0.f;
    for (int j = threadIdx.x; j < MM; j += 256) {
        r += fabsf(S[(size_t)i * MM + j]);
        c += fabsf(S[(size_t)j * MM + i]);
    }
    sr[threadIdx.x] = r; sc[threadIdx.x] = c;
    __syncthreads();
    for (int o = 128; o > 0; o >>= 1) {
        if (threadIdx.x < o) {
            sr[threadIdx.x] += sr[threadIdx.x + o];
            sc[threadIdx.x] += sc[threadIdx.x + o];
        }
        __syncthreads();
    }
    if (threadIdx.x == 0) {
        atomicMax((int*)&norms[0], __float_as_int(sr[0]));
        atomicMax((int*)&norms[1], __float_as_int(sc[0]));
    }
}
__global__ void init_X_kernel(const float* __restrict__ S,
                              const float* __restrict__ norms,
                              float* __restrict__ X) {
    const float scale = 1.f / (norms[0] * norms[1]);
    const int idx = blockIdx.x * blockDim.x + threadIdx.x;
    const int i = idx / MM, j = idx % MM;
    X[idx] = S[(size_t)j * MM + i] * scale;
}

// ---------------- host-side dispatch ----------------------------------------
static void gemm32(int M, int N, int K, const float* A, const float* B,
                   const float* Cin, float* C, float alpha, float beta)
{
    dim3 g(N / 64, M / 64);
    sgemm<64, 64, 16, 4, 4><<<g, 256>>>(M, N, K, A, B, Cin, C, alpha, beta);
}

static __nv_bfloat16 *s_Ah, *s_Al, *s_Bh, *s_Bl;

static void gemmbf(int M, int N, int K, const float* Cin, float* C,
                   float alpha, float beta)
{
    dim3 g(N / 128, M / 128);
    bf16gemm<<<g, 256>>>(M, N, K, s_Ah, s_Al, s_Bh, s_Bl, Cin, C, alpha, beta);
}
static void splitA(const float* src, int n) {
    split_kernel<<<(n / 4 + 255) / 256, 256>>>((const float4*)src, s_Ah, s_Al, n / 4);
}
static void splitB(const float* src, int n) {
    split_kernel<<<(n / 4 + 255) / 256, 256>>>((const float4*)src, s_Bh, s_Bl, n / 4);
}
static void splitTB(const float* src, int R, int C) {  // B planes = src^T
    splitT_kernel<<<dim3(C / 32, R / 32), dim3(32, 8)>>>(src, s_Bh, s_Bl, R, C);
}

extern "C" void kernel_launch(void* const* d_in, const int* in_sizes, int n_in,
                              void* d_out, int out_size)
{
    (void)in_sizes; (void)n_in; (void)out_size;
    const float* state     = (const float*)d_in[0];
    const float* state_cov = (const float*)d_in[1];
    const float* meas      = (const float*)d_in[2];
    const float* control   = (const float*)d_in[3];
    const float* F         = (const float*)d_in[4];
    const float* Q         = (const float*)d_in[5];
    const float* Bc        = (const float*)d_in[6];
    const float* H         = (const float*)d_in[7];
    const float* R         = (const float*)d_in[8];
    float* out_state = (float*)d_out;
    float* out_cov   = out_state + (size_t)DD * BB;

    float *sp, *fs, *cp, *innov, *hp, *S, *X, *X2, *T, *pht, *Kg, *norms;
    cudaGetSymbolAddress((void**)&sp,    g_state_p);
    cudaGetSymbolAddress((void**)&fs,    g_FS);
    cudaGetSymbolAddress((void**)&cp,    g_cov_p);
    cudaGetSymbolAddress((void**)&innov, g_innov);
    cudaGetSymbolAddress((void**)&hp,    g_HP);
    cudaGetSymbolAddress((void**)&S,     g_S);
    cudaGetSymbolAddress((void**)&X,     g_X);
    cudaGetSymbolAddress((void**)&X2,    g_X2);
    cudaGetSymbolAddress((void**)&T,     g_T);
    cudaGetSymbolAddress((void**)&pht,   g_PHt);
    cudaGetSymbolAddress((void**)&Kg,    g_K);
    cudaGetSymbolAddress((void**)&norms, g_norms);
    cudaGetSymbolAddress((void**)&s_Ah,  g_Ah);
    cudaGetSymbolAddress((void**)&s_Al,  g_Al);
    cudaGetSymbolAddress((void**)&s_Bh,  g_Bh);
    cudaGetSymbolAddress((void**)&s_Bl,  g_Bl);

    // ---- prediction ----
    splitA(F, DD * DD);
    splitB(state, DD * BB);
    gemmbf(DD, BB, DD, nullptr, sp, 1.f, 0.f);            // sp = F @ state
    splitB(state_cov, DD * DD);
    gemmbf(DD, DD, DD, nullptr, fs, 1.f, 0.f);            // fs = F @ Sigma
    splitA(fs, DD * DD);
    splitTB(F, DD, DD);
    gemmbf(DD, DD, DD, Q, cp, 1.f, 1.f);                  // cp = fs @ F^T + Q
    splitA(Bc, DD * CC);
    splitB(control, CC * BB);
    gemmbf(DD, BB, CC, sp, sp, 1.f, 1.f);                 // sp += Bc @ control

    // ---- correction ----
    splitA(H, MM * DD);
    splitB(sp, DD * BB);
    gemmbf(MM, BB, DD, meas, innov, -1.f, 1.f);           // innov = meas - H @ sp
    splitB(cp, DD * DD);
    gemmbf(MM, DD, DD, nullptr, hp, 1.f, 0.f);            // hp = H @ cp
    splitA(hp, MM * DD);
    splitTB(H, MM, DD);
    gemmbf(MM, MM, DD, R, S, 1.f, 1.f);                   // S = hp @ H^T + R
    splitA(cp, DD * DD);
    gemmbf(DD, MM, DD, nullptr, pht, 1.f, 0.f);           // pht = cp @ H^T

    // ---- Newton-Schulz inverse of S (fp32 SIMT) ----
    zero_norms_kernel<<<1, 32>>>(norms);
    snorms_kernel<<<MM, 256>>>(S, norms);
    init_X_kernel<<<(MM * MM) / 256, 256>>>(S, norms, X);
    float* cur = X;
    float* nxt = X2;
    for (int it = 0; it < NS_ITERS; ++it) {
        gemm32(MM, MM, MM, S,   cur, nullptr, T,   1.f, 0.f);   // T = S @ X
        gemm32(MM, MM, MM, cur, T,   cur,     nxt, -1.f, 2.f);  // X' = 2X - X@T
        float* tmpp = cur; cur = nxt; nxt = tmpp;
    }
    // cur == S^{-1}

    // ---- gain + outputs ----
    splitA(pht, DD * MM);
    splitB(cur, MM * MM);
    gemmbf(DD, MM, MM, nullptr, Kg, 1.f, 0.f);            // K = pht @ S^{-1}
    splitA(Kg, DD * MM);
    splitB(innov, MM * BB);
    gemmbf(DD, BB, MM, sp, out_state, 1.f, 1.f);          // state_n = sp + K@innov
    splitB(hp, MM * DD);
    gemmbf(DD, DD, MM, cp, out_cov, -1.f, 1.f);           // cov_n = cp - K@hp
}